// round 7
// baseline (speedup 1.0000x reference)
#include <cuda_runtime.h>

// SpatialTransformer: out[b,c,d,h,w] = trilinear_sample(src[b,c], (w,h,d)+flow[b,:,d,h,w])
// align_corners=True normalization cancels; padding_mode='zeros'.
//
// R7: occupancy push. R6 (32 warps/SM) was still latency-bound with no pipe
// saturated -> scale warps. Tile 32x8x8, R=3 -> 39x15x15 float2 = 70.2KB smem,
// 3 blocks x 512 threads = 48 warps/SM (75%). launch_bounds(512,3) caps regs
// at ~42 so the register file fits 1536 threads. Each of 16 warps covers
// (y = warp&7, z-half = warp>>3) and gathers 4 z slices.
// Gather via LDS (no 32B sector overfetch). |flow|>3 (~0.8%) -> exact global path.

#define Dz 160
#define Hy 192
#define Wx 160
#define Bn 2
#define HW (Hy * Wx)            // 30720
#define DHW (Dz * Hy * Wx)      // 4915200

#define RH 3                    // halo radius
#define TX 32
#define TY 8
#define TZ 8
#define EX (TX + 2 * RH + 1)    // 39
#define EY (TY + 2 * RH + 1)    // 15
#define EZ (TZ + 2 * RH + 1)    // 15
#define NROWS (EY * EZ)         // 225
#define ESZ (EX * NROWS)        // 8775
#define SMEM_BYTES (ESZ * (int)sizeof(float2))   // 70200

#define NTHREADS 512
#define NWARPS (NTHREADS / 32)  // 16
#define KZ_PER_THREAD (TZ / 2)  // 4

__global__ __launch_bounds__(NTHREADS, 3) void warp3d_tiled(
    const float* __restrict__ src,
    const float* __restrict__ flow,
    float* __restrict__ out)
{
    extern __shared__ float2 tile[];

    int bx = blockIdx.x;            // 0..4   (x tiles, 160/32)
    int by = blockIdx.y;            // 0..23  (y tiles, 192/8)
    int bzb = blockIdx.z;           // 0..39  (z tiles * batch)
    int b  = bzb / (Dz / TZ);
    int bz = bzb % (Dz / TZ);

    int x_org = bx * TX - RH;
    int y_org = by * TY - RH;
    int z_org = bz * TZ - RH;

    const float* c0 = src + (size_t)b * 2 * DHW;
    const float* c1 = c0 + DHW;

    int lane = threadIdx.x & 31;
    int warp = threadIdx.x >> 5;    // 0..15

    // ---- Fill: each warp copies whole (ez,ey) rows, coalesced strips ----
    for (int r = warp; r < NROWS; r += NWARPS) {
        int ey = r % EY;
        int ez = r / EY;
        int gy = min(max(y_org + ey, 0), Hy - 1);
        int gz = min(max(z_org + ez, 0), Dz - 1);
        const float* r0 = c0 + (gz * Hy + gy) * Wx;
        const float* r1 = c1 + (gz * Hy + gy) * Wx;
        float2* trow = tile + r * EX;

        int gx0 = min(max(x_org + lane, 0), Wx - 1);
        trow[lane] = make_float2(__ldg(r0 + gx0), __ldg(r1 + gx0));
        int ex = lane + 32;
        if (ex < EX) {
            int gx1 = min(max(x_org + ex, 0), Wx - 1);
            trow[ex] = make_float2(__ldg(r0 + gx1), __ldg(r1 + gx1));
        }
    }
    __syncthreads();

    // ---- Gather: lane = x, warp&7 = y, warp>>3 = z-half (4 slices each) ----
    int w = bx * TX + lane;
    int h = by * TY + (warp & 7);
    int kz0 = (warp >> 3) * KZ_PER_THREAD;

    const float* fb = flow + (size_t)b * 3 * DHW;
    float* ob = out + (size_t)b * 2 * DHW;

    int s_base = ((bz * TZ + kz0) * Hy + h) * Wx + w;

    #pragma unroll
    for (int i = 0; i < KZ_PER_THREAD; i++) {
        int d = bz * TZ + kz0 + i;
        int s = s_base + i * HW;

        float x = (float)w + __ldg(fb + s);
        float y = (float)h + __ldg(fb + s + DHW);
        float z = (float)d + __ldg(fb + s + 2 * DHW);

        float x0f = floorf(x), y0f = floorf(y), z0f = floorf(z);
        float fx = x - x0f, fy = y - y0f, fz = z - z0f;
        int x0 = (int)x0f, y0 = (int)y0f, z0 = (int)z0f;
        int x1 = x0 + 1, y1 = y0 + 1, z1 = z0 + 1;

        // Per-axis weights, zeroed when that corner is outside the volume.
        float wx0 = (x0 >= 0 && x0 < Wx) ? (1.0f - fx) : 0.0f;
        float wx1 = (x1 >= 0 && x1 < Wx) ? fx          : 0.0f;
        float wy0 = (y0 >= 0 && y0 < Hy) ? (1.0f - fy) : 0.0f;
        float wy1 = (y1 >= 0 && y1 < Hy) ? fy          : 0.0f;
        float wz0 = (z0 >= 0 && z0 < Dz) ? (1.0f - fz) : 0.0f;
        float wz1 = (z1 >= 0 && z1 < Dz) ? fz          : 0.0f;

        float w00 = wz0 * wy0, w01 = wz0 * wy1;
        float w10 = wz1 * wy0, w11 = wz1 * wy1;

        int lx = x0 - x_org;
        int ly = y0 - y_org;
        int lz = z0 - z_org;

        float acc0, acc1;
        if (lx >= 0 && lx + 1 < EX &&
            ly >= 0 && ly + 1 < EY &&
            lz >= 0 && lz + 1 < EZ) {
            // In-tile: 8 corners from smem (tile holds clamped values; zero
            // weights kill out-of-volume contributions, matching reference).
            const float2* t00 = tile + (lz * EY + ly) * EX + lx;
            const float2* t10 = t00 + EY * EX;
            float2 v000 = t00[0],  v001 = t00[1];
            float2 v010 = t00[EX], v011 = t00[EX + 1];
            float2 v100 = t10[0],  v101 = t10[1];
            float2 v110 = t10[EX], v111 = t10[EX + 1];

            float lo0 = w00 * v000.x + w01 * v010.x + w10 * v100.x + w11 * v110.x;
            float hi0 = w00 * v001.x + w01 * v011.x + w10 * v101.x + w11 * v111.x;
            float lo1 = w00 * v000.y + w01 * v010.y + w10 * v100.y + w11 * v110.y;
            float hi1 = w00 * v001.y + w01 * v011.y + w10 * v101.y + w11 * v111.y;

            acc0 = wx0 * lo0 + wx1 * hi0;
            acc1 = wx0 * lo1 + wx1 * hi1;
        } else {
            // Rare fallback (|flow| > RH): exact global-path gather.
            int x0c = min(max(x0, 0), Wx - 1);
            int x1c = min(max(x1, 0), Wx - 1);
            int y0c = min(max(y0, 0), Hy - 1);
            int y1c = min(max(y1, 0), Hy - 1);
            int z0c = min(max(z0, 0), Dz - 1);
            int z1c = min(max(z1, 0), Dz - 1);

            int zy00 = z0c * HW + y0c * Wx;
            int zy01 = z0c * HW + y1c * Wx;
            int zy10 = z1c * HW + y0c * Wx;
            int zy11 = z1c * HW + y1c * Wx;

            float w000 = w00 * wx0, w001 = w00 * wx1;
            float w010 = w01 * wx0, w011 = w01 * wx1;
            float w100 = w10 * wx0, w101 = w10 * wx1;
            float w110 = w11 * wx0, w111 = w11 * wx1;

            acc0  = w000 * __ldg(c0 + zy00 + x0c) + w001 * __ldg(c0 + zy00 + x1c);
            acc0 += w010 * __ldg(c0 + zy01 + x0c) + w011 * __ldg(c0 + zy01 + x1c);
            acc0 += w100 * __ldg(c0 + zy10 + x0c) + w101 * __ldg(c0 + zy10 + x1c);
            acc0 += w110 * __ldg(c0 + zy11 + x0c) + w111 * __ldg(c0 + zy11 + x1c);

            acc1  = w000 * __ldg(c1 + zy00 + x0c) + w001 * __ldg(c1 + zy00 + x1c);
            acc1 += w010 * __ldg(c1 + zy01 + x0c) + w011 * __ldg(c1 + zy01 + x1c);
            acc1 += w100 * __ldg(c1 + zy10 + x0c) + w101 * __ldg(c1 + zy10 + x1c);
            acc1 += w110 * __ldg(c1 + zy11 + x0c) + w111 * __ldg(c1 + zy11 + x1c);
        }

        ob[s] = acc0;
        ob[DHW + s] = acc1;
    }
}

extern "C" void kernel_launch(void* const* d_in, const int* in_sizes, int n_in,
                              void* d_out, int out_size) {
    const float* src  = (const float*)d_in[0];
    const float* flow = (const float*)d_in[1];
    float* out = (float*)d_out;

    cudaFuncSetAttribute(warp3d_tiled,
                         cudaFuncAttributeMaxDynamicSharedMemorySize, SMEM_BYTES);

    dim3 grid(Wx / TX, Hy / TY, (Dz / TZ) * Bn);
    warp3d_tiled<<<grid, NTHREADS, SMEM_BYTES>>>(src, flow, out);
}

// round 8
// speedup vs baseline: 1.0030x; 1.0030x over previous
#include <cuda_runtime.h>

// SpatialTransformer: out[b,c,d,h,w] = trilinear_sample(src[b,c], (w,h,d)+flow[b,:,d,h,w])
// align_corners=True normalization cancels; padding_mode='zeros'.
//
// R8: instruction-count cut. R7 showed more warps does NOT help (issue-bound per
// warp, alu 42%). Keep R6 tile (32x16x8, R=3, 107.6KB smem, 2 blocks x 512 = 32
// warps) but each thread processes an x-QUAD of 4 voxels: flow = 3 LDG.128/quad
// (was 12 LDG.32), out = 2 STG.128/quad (was 8 STG.32). LDS gather unchanged.
// |flow|>3 (~0.8% of voxels) -> exact global-path fallback.

#define Dz 160
#define Hy 192
#define Wx 160
#define Bn 2
#define HW (Hy * Wx)            // 30720
#define DHW (Dz * Hy * Wx)      // 4915200

#define RH 3                    // halo radius
#define TX 32
#define TY 16
#define TZ 8
#define EX (TX + 2 * RH + 1)    // 39
#define EY (TY + 2 * RH + 1)    // 23
#define EZ (TZ + 2 * RH + 1)    // 15
#define NROWS (EY * EZ)         // 345
#define ESZ (EX * NROWS)        // 13455
#define SMEM_BYTES (ESZ * (int)sizeof(float2))   // 107640

#define NTHREADS 512
#define NWARPS (NTHREADS / 32)  // 16

__global__ __launch_bounds__(NTHREADS, 2) void warp3d_tiled(
    const float* __restrict__ src,
    const float* __restrict__ flow,
    float* __restrict__ out)
{
    extern __shared__ float2 tile[];

    int bx = blockIdx.x;            // 0..4   (x tiles, 160/32)
    int by = blockIdx.y;            // 0..11  (y tiles, 192/16)
    int bzb = blockIdx.z;           // 0..39  (z tiles * batch)
    int b  = bzb / (Dz / TZ);
    int bz = bzb % (Dz / TZ);

    int x_org = bx * TX - RH;
    int y_org = by * TY - RH;
    int z_org = bz * TZ - RH;

    const float* c0 = src + (size_t)b * 2 * DHW;
    const float* c1 = c0 + DHW;

    int lane = threadIdx.x & 31;
    int warp = threadIdx.x >> 5;    // 0..15

    // ---- Fill: each warp copies whole (ez,ey) rows, coalesced strips ----
    for (int r = warp; r < NROWS; r += NWARPS) {
        int ey = r % EY;
        int ez = r / EY;
        int gy = min(max(y_org + ey, 0), Hy - 1);
        int gz = min(max(z_org + ez, 0), Dz - 1);
        const float* r0 = c0 + (gz * Hy + gy) * Wx;
        const float* r1 = c1 + (gz * Hy + gy) * Wx;
        float2* trow = tile + r * EX;

        int gx0 = min(max(x_org + lane, 0), Wx - 1);
        trow[lane] = make_float2(__ldg(r0 + gx0), __ldg(r1 + gx0));
        int ex = lane + 32;
        if (ex < EX) {
            int gx1 = min(max(x_org + ex, 0), Wx - 1);
            trow[ex] = make_float2(__ldg(r0 + gx1), __ldg(r1 + gx1));
        }
    }
    __syncthreads();

    // ---- Gather: thread -> x-quad. t = qx(3b) | yy(4b) | zpair(2b) ----
    int t = threadIdx.x;
    int qx = t & 7;                 // x-quad 0..7
    int yy = (t >> 3) & 15;         // y 0..15
    int zp = t >> 7;                // 0..3 (z pair)

    int w0 = bx * TX + qx * 4;
    int h  = by * TY + yy;

    const float* fb = flow + (size_t)b * 3 * DHW;
    float* ob = out + (size_t)b * 2 * DHW;

    #pragma unroll
    for (int i = 0; i < 2; i++) {
        int kz = zp * 2 + i;
        int d = bz * TZ + kz;
        int s = (d * Hy + h) * Wx + w0;         // 16B-aligned (w0 % 4 == 0)

        float4 fxv = __ldg((const float4*)(fb + s));
        float4 fyv = __ldg((const float4*)(fb + s + DHW));
        float4 fzv = __ldg((const float4*)(fb + s + 2 * DHW));
        float fxs[4] = {fxv.x, fxv.y, fxv.z, fxv.w};
        float fys[4] = {fyv.x, fyv.y, fyv.z, fyv.w};
        float fzs[4] = {fzv.x, fzv.y, fzv.z, fzv.w};

        float acc0[4], acc1[4];

        #pragma unroll
        for (int v = 0; v < 4; v++) {
            float x = (float)(w0 + v) + fxs[v];
            float y = (float)h + fys[v];
            float z = (float)d + fzs[v];

            float x0f = floorf(x), y0f = floorf(y), z0f = floorf(z);
            float fx = x - x0f, fy = y - y0f, fz = z - z0f;
            int x0 = (int)x0f, y0 = (int)y0f, z0 = (int)z0f;
            int x1 = x0 + 1, y1 = y0 + 1, z1 = z0 + 1;

            float wx0 = (x0 >= 0 && x0 < Wx) ? (1.0f - fx) : 0.0f;
            float wx1 = (x1 >= 0 && x1 < Wx) ? fx          : 0.0f;
            float wy0 = (y0 >= 0 && y0 < Hy) ? (1.0f - fy) : 0.0f;
            float wy1 = (y1 >= 0 && y1 < Hy) ? fy          : 0.0f;
            float wz0 = (z0 >= 0 && z0 < Dz) ? (1.0f - fz) : 0.0f;
            float wz1 = (z1 >= 0 && z1 < Dz) ? fz          : 0.0f;

            float w00 = wz0 * wy0, w01 = wz0 * wy1;
            float w10 = wz1 * wy0, w11 = wz1 * wy1;

            int lx = x0 - x_org;
            int ly = y0 - y_org;
            int lz = z0 - z_org;

            if (lx >= 0 && lx + 1 < EX &&
                ly >= 0 && ly + 1 < EY &&
                lz >= 0 && lz + 1 < EZ) {
                const float2* t00 = tile + (lz * EY + ly) * EX + lx;
                const float2* t10 = t00 + EY * EX;
                float2 v000 = t00[0],  v001 = t00[1];
                float2 v010 = t00[EX], v011 = t00[EX + 1];
                float2 v100 = t10[0],  v101 = t10[1];
                float2 v110 = t10[EX], v111 = t10[EX + 1];

                float lo0 = w00 * v000.x + w01 * v010.x + w10 * v100.x + w11 * v110.x;
                float hi0 = w00 * v001.x + w01 * v011.x + w10 * v101.x + w11 * v111.x;
                float lo1 = w00 * v000.y + w01 * v010.y + w10 * v100.y + w11 * v110.y;
                float hi1 = w00 * v001.y + w01 * v011.y + w10 * v101.y + w11 * v111.y;

                acc0[v] = wx0 * lo0 + wx1 * hi0;
                acc1[v] = wx0 * lo1 + wx1 * hi1;
            } else {
                // Rare fallback (|flow| > RH): exact global-path gather.
                int x0c = min(max(x0, 0), Wx - 1);
                int x1c = min(max(x1, 0), Wx - 1);
                int y0c = min(max(y0, 0), Hy - 1);
                int y1c = min(max(y1, 0), Hy - 1);
                int z0c = min(max(z0, 0), Dz - 1);
                int z1c = min(max(z1, 0), Dz - 1);

                int zy00 = z0c * HW + y0c * Wx;
                int zy01 = z0c * HW + y1c * Wx;
                int zy10 = z1c * HW + y0c * Wx;
                int zy11 = z1c * HW + y1c * Wx;

                float w000 = w00 * wx0, w001 = w00 * wx1;
                float w010 = w01 * wx0, w011 = w01 * wx1;
                float w100 = w10 * wx0, w101 = w10 * wx1;
                float w110 = w11 * wx0, w111 = w11 * wx1;

                float a0, a1;
                a0  = w000 * __ldg(c0 + zy00 + x0c) + w001 * __ldg(c0 + zy00 + x1c);
                a0 += w010 * __ldg(c0 + zy01 + x0c) + w011 * __ldg(c0 + zy01 + x1c);
                a0 += w100 * __ldg(c0 + zy10 + x0c) + w101 * __ldg(c0 + zy10 + x1c);
                a0 += w110 * __ldg(c0 + zy11 + x0c) + w111 * __ldg(c0 + zy11 + x1c);

                a1  = w000 * __ldg(c1 + zy00 + x0c) + w001 * __ldg(c1 + zy00 + x1c);
                a1 += w010 * __ldg(c1 + zy01 + x0c) + w011 * __ldg(c1 + zy01 + x1c);
                a1 += w100 * __ldg(c1 + zy10 + x0c) + w101 * __ldg(c1 + zy10 + x1c);
                a1 += w110 * __ldg(c1 + zy11 + x0c) + w111 * __ldg(c1 + zy11 + x1c);

                acc0[v] = a0;
                acc1[v] = a1;
            }
        }

        *(float4*)(ob + s)       = make_float4(acc0[0], acc0[1], acc0[2], acc0[3]);
        *(float4*)(ob + DHW + s) = make_float4(acc1[0], acc1[1], acc1[2], acc1[3]);
    }
}

extern "C" void kernel_launch(void* const* d_in, const int* in_sizes, int n_in,
                              void* d_out, int out_size) {
    const float* src  = (const float*)d_in[0];
    const float* flow = (const float*)d_in[1];
    float* out = (float*)d_out;

    cudaFuncSetAttribute(warp3d_tiled,
                         cudaFuncAttributeMaxDynamicSharedMemorySize, SMEM_BYTES);

    dim3 grid(Wx / TX, Hy / TY, (Dz / TZ) * Bn);
    warp3d_tiled<<<grid, NTHREADS, SMEM_BYTES>>>(src, flow, out);
}

// round 9
// speedup vs baseline: 1.0630x; 1.0598x over previous
#include <cuda_runtime.h>

// SpatialTransformer: out[b,c,d,h,w] = trilinear_sample(src[b,c], (w,h,d)+flow[b,:,d,h,w])
// align_corners=True normalization cancels; padding_mode='zeros'.
//
// R9: R6 winner (tile 32x16x8, R=3, 107.6KB smem, 2 blocks x 512 = 32 warps)
// + flow PREFETCH: each thread issues its 24 flow LDGs (8 voxels x 3 comps)
// BEFORE the smem fill loop, so flow DRAM latency overlaps the fill phase and
// the post-barrier gather runs stall-free on LDS+FMA only.
// |flow|>3 near tile edges (~0.1%) -> exact global-path fallback.

#define Dz 160
#define Hy 192
#define Wx 160
#define Bn 2
#define HW (Hy * Wx)            // 30720
#define DHW (Dz * Hy * Wx)      // 4915200

#define RH 3                    // halo radius
#define TX 32
#define TY 16
#define TZ 8
#define EX (TX + 2 * RH + 1)    // 39
#define EY (TY + 2 * RH + 1)    // 23
#define EZ (TZ + 2 * RH + 1)    // 15
#define NROWS (EY * EZ)         // 345
#define ESZ (EX * NROWS)        // 13455
#define SMEM_BYTES (ESZ * (int)sizeof(float2))   // 107640

#define NTHREADS 512
#define NWARPS (NTHREADS / 32)  // 16

__global__ __launch_bounds__(NTHREADS, 2) void warp3d_tiled(
    const float* __restrict__ src,
    const float* __restrict__ flow,
    float* __restrict__ out)
{
    extern __shared__ float2 tile[];

    int bx = blockIdx.x;            // 0..4   (x tiles, 160/32)
    int by = blockIdx.y;            // 0..11  (y tiles, 192/16)
    int bzb = blockIdx.z;           // 0..39  (z tiles * batch)
    int b  = bzb / (Dz / TZ);
    int bz = bzb % (Dz / TZ);

    int x_org = bx * TX - RH;
    int y_org = by * TY - RH;
    int z_org = bz * TZ - RH;

    const float* c0 = src + (size_t)b * 2 * DHW;
    const float* c1 = c0 + DHW;

    int lane = threadIdx.x & 31;
    int warp = threadIdx.x >> 5;    // 0..15

    // Gather-phase coordinates (lane = x, warp = y, loop over 8 z slices)
    int w = bx * TX + lane;
    int h = by * TY + warp;
    const float* fb = flow + (size_t)b * 3 * DHW;
    int s_base = ((bz * TZ) * Hy + h) * Wx + w;

    // ---- Prefetch flow for this thread's 8 voxels (DRAM latency overlaps fill) ----
    float pfx[TZ], pfy[TZ], pfz[TZ];
    #pragma unroll
    for (int kz = 0; kz < TZ; kz++) {
        int s = s_base + kz * HW;
        pfx[kz] = __ldg(fb + s);
        pfy[kz] = __ldg(fb + s + DHW);
        pfz[kz] = __ldg(fb + s + 2 * DHW);
    }

    // ---- Fill: each warp copies whole (ez,ey) rows, coalesced strips ----
    for (int r = warp; r < NROWS; r += NWARPS) {
        int ey = r % EY;
        int ez = r / EY;
        int gy = min(max(y_org + ey, 0), Hy - 1);
        int gz = min(max(z_org + ez, 0), Dz - 1);
        const float* r0 = c0 + (gz * Hy + gy) * Wx;
        const float* r1 = c1 + (gz * Hy + gy) * Wx;
        float2* trow = tile + r * EX;

        int gx0 = min(max(x_org + lane, 0), Wx - 1);
        trow[lane] = make_float2(__ldg(r0 + gx0), __ldg(r1 + gx0));
        int ex = lane + 32;
        if (ex < EX) {
            int gx1 = min(max(x_org + ex, 0), Wx - 1);
            trow[ex] = make_float2(__ldg(r0 + gx1), __ldg(r1 + gx1));
        }
    }
    __syncthreads();

    float* ob = out + (size_t)b * 2 * DHW;

    #pragma unroll
    for (int kz = 0; kz < TZ; kz++) {
        int d = bz * TZ + kz;
        int s = s_base + kz * HW;

        float x = (float)w + pfx[kz];
        float y = (float)h + pfy[kz];
        float z = (float)d + pfz[kz];

        float x0f = floorf(x), y0f = floorf(y), z0f = floorf(z);
        float fx = x - x0f, fy = y - y0f, fz = z - z0f;
        int x0 = (int)x0f, y0 = (int)y0f, z0 = (int)z0f;
        int x1 = x0 + 1, y1 = y0 + 1, z1 = z0 + 1;

        // Per-axis weights, zeroed when that corner is outside the volume.
        float wx0 = (x0 >= 0 && x0 < Wx) ? (1.0f - fx) : 0.0f;
        float wx1 = (x1 >= 0 && x1 < Wx) ? fx          : 0.0f;
        float wy0 = (y0 >= 0 && y0 < Hy) ? (1.0f - fy) : 0.0f;
        float wy1 = (y1 >= 0 && y1 < Hy) ? fy          : 0.0f;
        float wz0 = (z0 >= 0 && z0 < Dz) ? (1.0f - fz) : 0.0f;
        float wz1 = (z1 >= 0 && z1 < Dz) ? fz          : 0.0f;

        float w00 = wz0 * wy0, w01 = wz0 * wy1;
        float w10 = wz1 * wy0, w11 = wz1 * wy1;

        int lx = x0 - x_org;
        int ly = y0 - y_org;
        int lz = z0 - z_org;

        float acc0, acc1;
        if (lx >= 0 && lx + 1 < EX &&
            ly >= 0 && ly + 1 < EY &&
            lz >= 0 && lz + 1 < EZ) {
            // In-tile: 8 corners from smem (tile holds clamped values; zero
            // weights kill out-of-volume contributions, matching reference).
            const float2* t00 = tile + (lz * EY + ly) * EX + lx;
            const float2* t10 = t00 + EY * EX;
            float2 v000 = t00[0],  v001 = t00[1];
            float2 v010 = t00[EX], v011 = t00[EX + 1];
            float2 v100 = t10[0],  v101 = t10[1];
            float2 v110 = t10[EX], v111 = t10[EX + 1];

            float lo0 = w00 * v000.x + w01 * v010.x + w10 * v100.x + w11 * v110.x;
            float hi0 = w00 * v001.x + w01 * v011.x + w10 * v101.x + w11 * v111.x;
            float lo1 = w00 * v000.y + w01 * v010.y + w10 * v100.y + w11 * v110.y;
            float hi1 = w00 * v001.y + w01 * v011.y + w10 * v101.y + w11 * v111.y;

            acc0 = wx0 * lo0 + wx1 * hi0;
            acc1 = wx0 * lo1 + wx1 * hi1;
        } else {
            // Rare fallback (|flow| > RH near tile edge): exact global-path gather.
            int x0c = min(max(x0, 0), Wx - 1);
            int x1c = min(max(x1, 0), Wx - 1);
            int y0c = min(max(y0, 0), Hy - 1);
            int y1c = min(max(y1, 0), Hy - 1);
            int z0c = min(max(z0, 0), Dz - 1);
            int z1c = min(max(z1, 0), Dz - 1);

            int zy00 = z0c * HW + y0c * Wx;
            int zy01 = z0c * HW + y1c * Wx;
            int zy10 = z1c * HW + y0c * Wx;
            int zy11 = z1c * HW + y1c * Wx;

            float w000 = w00 * wx0, w001 = w00 * wx1;
            float w010 = w01 * wx0, w011 = w01 * wx1;
            float w100 = w10 * wx0, w101 = w10 * wx1;
            float w110 = w11 * wx0, w111 = w11 * wx1;

            acc0  = w000 * __ldg(c0 + zy00 + x0c) + w001 * __ldg(c0 + zy00 + x1c);
            acc0 += w010 * __ldg(c0 + zy01 + x0c) + w011 * __ldg(c0 + zy01 + x1c);
            acc0 += w100 * __ldg(c0 + zy10 + x0c) + w101 * __ldg(c0 + zy10 + x1c);
            acc0 += w110 * __ldg(c0 + zy11 + x0c) + w111 * __ldg(c0 + zy11 + x1c);

            acc1  = w000 * __ldg(c1 + zy00 + x0c) + w001 * __ldg(c1 + zy00 + x1c);
            acc1 += w010 * __ldg(c1 + zy01 + x0c) + w011 * __ldg(c1 + zy01 + x1c);
            acc1 += w100 * __ldg(c1 + zy10 + x0c) + w101 * __ldg(c1 + zy10 + x1c);
            acc1 += w110 * __ldg(c1 + zy11 + x0c) + w111 * __ldg(c1 + zy11 + x1c);
        }

        ob[s] = acc0;
        ob[DHW + s] = acc1;
    }
}

extern "C" void kernel_launch(void* const* d_in, const int* in_sizes, int n_in,
                              void* d_out, int out_size) {
    const float* src  = (const float*)d_in[0];
    const float* flow = (const float*)d_in[1];
    float* out = (float*)d_out;

    cudaFuncSetAttribute(warp3d_tiled,
                         cudaFuncAttributeMaxDynamicSharedMemorySize, SMEM_BYTES);

    dim3 grid(Wx / TX, Hy / TY, (Dz / TZ) * Bn);
    warp3d_tiled<<<grid, NTHREADS, SMEM_BYTES>>>(src, flow, out);
}

// round 10
// speedup vs baseline: 1.4192x; 1.3351x over previous
#include <cuda_runtime.h>
#include <cuda_fp16.h>

// SpatialTransformer: out[b,c,d,h,w] = trilinear_sample(src[b,c], (w,h,d)+flow[b,:,d,h,w])
// align_corners=True normalization cancels; padding_mode='zeros'.
//
// R10: fp16 smem tile. Corner values stored as half2 (c0,c1) -> tile 53.8KB,
// 3 blocks x 512 = 48 warps/SM at the SAME 3.3x fill overfetch as the R6 winner.
// Gather = 8 LDS.32/voxel (was 8 LDS.64), STS bytes halved. Weights + accumulation
// remain fp32; only corner values are quantized (expected rel_err ~3e-4 < 1e-3).
// |flow|>3 (~0.8%) -> exact fp32 global-path fallback.

#define Dz 160
#define Hy 192
#define Wx 160
#define Bn 2
#define HW (Hy * Wx)            // 30720
#define DHW (Dz * Hy * Wx)      // 4915200

#define RH 3                    // halo radius
#define TX 32
#define TY 16
#define TZ 8
#define EX (TX + 2 * RH + 1)    // 39
#define EY (TY + 2 * RH + 1)    // 23
#define EZ (TZ + 2 * RH + 1)    // 15
#define NROWS (EY * EZ)         // 345
#define ESZ (EX * NROWS)        // 13455
#define SMEM_BYTES (ESZ * (int)sizeof(__half2))  // 53820

#define NTHREADS 512
#define NWARPS (NTHREADS / 32)  // 16

__global__ __launch_bounds__(NTHREADS, 3) void warp3d_tiled(
    const float* __restrict__ src,
    const float* __restrict__ flow,
    float* __restrict__ out)
{
    extern __shared__ __half2 tile[];

    int bx = blockIdx.x;            // 0..4   (x tiles, 160/32)
    int by = blockIdx.y;            // 0..11  (y tiles, 192/16)
    int bzb = blockIdx.z;           // 0..39  (z tiles * batch)
    int b  = bzb / (Dz / TZ);
    int bz = bzb % (Dz / TZ);

    int x_org = bx * TX - RH;
    int y_org = by * TY - RH;
    int z_org = bz * TZ - RH;

    const float* c0 = src + (size_t)b * 2 * DHW;
    const float* c1 = c0 + DHW;

    int lane = threadIdx.x & 31;
    int warp = threadIdx.x >> 5;    // 0..15

    // ---- Fill: each warp copies whole (ez,ey) rows, coalesced strips ----
    for (int r = warp; r < NROWS; r += NWARPS) {
        int ey = r % EY;
        int ez = r / EY;
        int gy = min(max(y_org + ey, 0), Hy - 1);
        int gz = min(max(z_org + ez, 0), Dz - 1);
        const float* r0 = c0 + (gz * Hy + gy) * Wx;
        const float* r1 = c1 + (gz * Hy + gy) * Wx;
        __half2* trow = tile + r * EX;

        int gx0 = min(max(x_org + lane, 0), Wx - 1);
        trow[lane] = __floats2half2_rn(__ldg(r0 + gx0), __ldg(r1 + gx0));
        int ex = lane + 32;
        if (ex < EX) {
            int gx1 = min(max(x_org + ex, 0), Wx - 1);
            trow[ex] = __floats2half2_rn(__ldg(r0 + gx1), __ldg(r1 + gx1));
        }
    }
    __syncthreads();

    // ---- Gather: lane = x, warp = y (16 warps), loop over 8 z slices ----
    int w = bx * TX + lane;
    int h = by * TY + warp;

    const float* fb = flow + (size_t)b * 3 * DHW;
    float* ob = out + (size_t)b * 2 * DHW;

    int s_base = ((bz * TZ) * Hy + h) * Wx + w;

    #pragma unroll
    for (int kz = 0; kz < TZ; kz++) {
        int d = bz * TZ + kz;
        int s = s_base + kz * HW;

        float x = (float)w + __ldg(fb + s);
        float y = (float)h + __ldg(fb + s + DHW);
        float z = (float)d + __ldg(fb + s + 2 * DHW);

        float x0f = floorf(x), y0f = floorf(y), z0f = floorf(z);
        float fx = x - x0f, fy = y - y0f, fz = z - z0f;
        int x0 = (int)x0f, y0 = (int)y0f, z0 = (int)z0f;
        int x1 = x0 + 1, y1 = y0 + 1, z1 = z0 + 1;

        // Per-axis weights, zeroed when that corner is outside the volume.
        float wx0 = (x0 >= 0 && x0 < Wx) ? (1.0f - fx) : 0.0f;
        float wx1 = (x1 >= 0 && x1 < Wx) ? fx          : 0.0f;
        float wy0 = (y0 >= 0 && y0 < Hy) ? (1.0f - fy) : 0.0f;
        float wy1 = (y1 >= 0 && y1 < Hy) ? fy          : 0.0f;
        float wz0 = (z0 >= 0 && z0 < Dz) ? (1.0f - fz) : 0.0f;
        float wz1 = (z1 >= 0 && z1 < Dz) ? fz          : 0.0f;

        float w00 = wz0 * wy0, w01 = wz0 * wy1;
        float w10 = wz1 * wy0, w11 = wz1 * wy1;

        int lx = x0 - x_org;
        int ly = y0 - y_org;
        int lz = z0 - z_org;

        float acc0, acc1;
        if (lx >= 0 && lx + 1 < EX &&
            ly >= 0 && ly + 1 < EY &&
            lz >= 0 && lz + 1 < EZ) {
            // In-tile: 8 corners from smem (tile holds clamped values; zero
            // weights kill out-of-volume contributions, matching reference).
            const __half2* t00 = tile + (lz * EY + ly) * EX + lx;
            const __half2* t10 = t00 + EY * EX;
            float2 v000 = __half22float2(t00[0]);
            float2 v001 = __half22float2(t00[1]);
            float2 v010 = __half22float2(t00[EX]);
            float2 v011 = __half22float2(t00[EX + 1]);
            float2 v100 = __half22float2(t10[0]);
            float2 v101 = __half22float2(t10[1]);
            float2 v110 = __half22float2(t10[EX]);
            float2 v111 = __half22float2(t10[EX + 1]);

            float lo0 = w00 * v000.x + w01 * v010.x + w10 * v100.x + w11 * v110.x;
            float hi0 = w00 * v001.x + w01 * v011.x + w10 * v101.x + w11 * v111.x;
            float lo1 = w00 * v000.y + w01 * v010.y + w10 * v100.y + w11 * v110.y;
            float hi1 = w00 * v001.y + w01 * v011.y + w10 * v101.y + w11 * v111.y;

            acc0 = wx0 * lo0 + wx1 * hi0;
            acc1 = wx0 * lo1 + wx1 * hi1;
        } else {
            // Rare fallback (|flow| > RH): exact fp32 global-path gather.
            int x0c = min(max(x0, 0), Wx - 1);
            int x1c = min(max(x1, 0), Wx - 1);
            int y0c = min(max(y0, 0), Hy - 1);
            int y1c = min(max(y1, 0), Hy - 1);
            int z0c = min(max(z0, 0), Dz - 1);
            int z1c = min(max(z1, 0), Dz - 1);

            int zy00 = z0c * HW + y0c * Wx;
            int zy01 = z0c * HW + y1c * Wx;
            int zy10 = z1c * HW + y0c * Wx;
            int zy11 = z1c * HW + y1c * Wx;

            float w000 = w00 * wx0, w001 = w00 * wx1;
            float w010 = w01 * wx0, w011 = w01 * wx1;
            float w100 = w10 * wx0, w101 = w10 * wx1;
            float w110 = w11 * wx0, w111 = w11 * wx1;

            acc0  = w000 * __ldg(c0 + zy00 + x0c) + w001 * __ldg(c0 + zy00 + x1c);
            acc0 += w010 * __ldg(c0 + zy01 + x0c) + w011 * __ldg(c0 + zy01 + x1c);
            acc0 += w100 * __ldg(c0 + zy10 + x0c) + w101 * __ldg(c0 + zy10 + x1c);
            acc0 += w110 * __ldg(c0 + zy11 + x0c) + w111 * __ldg(c0 + zy11 + x1c);

            acc1  = w000 * __ldg(c1 + zy00 + x0c) + w001 * __ldg(c1 + zy00 + x1c);
            acc1 += w010 * __ldg(c1 + zy01 + x0c) + w011 * __ldg(c1 + zy01 + x1c);
            acc1 += w100 * __ldg(c1 + zy10 + x0c) + w101 * __ldg(c1 + zy10 + x1c);
            acc1 += w110 * __ldg(c1 + zy11 + x0c) + w111 * __ldg(c1 + zy11 + x1c);
        }

        ob[s] = acc0;
        ob[DHW + s] = acc1;
    }
}

extern "C" void kernel_launch(void* const* d_in, const int* in_sizes, int n_in,
                              void* d_out, int out_size) {
    const float* src  = (const float*)d_in[0];
    const float* flow = (const float*)d_in[1];
    float* out = (float*)d_out;

    cudaFuncSetAttribute(warp3d_tiled,
                         cudaFuncAttributeMaxDynamicSharedMemorySize, SMEM_BYTES);

    dim3 grid(Wx / TX, Hy / TY, (Dz / TZ) * Bn);
    warp3d_tiled<<<grid, NTHREADS, SMEM_BYTES>>>(src, flow, out);
}

// round 11
// speedup vs baseline: 1.5534x; 1.0946x over previous
#include <cuda_runtime.h>
#include <cuda_fp16.h>

// SpatialTransformer: out[b,c,d,h,w] = trilinear_sample(src[b,c], (w,h,d)+flow[b,:,d,h,w])
// align_corners=True normalization cancels; padding_mode='zeros'.
//
// R11: R10 winner (half2 tile 53.8KB, 3 blocks x 512 = 48 warps) + ALU diet:
//  - interior blocks (tile strictly inside volume, 45% of blocks) skip all
//    volume bound predicates (in-tile test already implies in-volume),
//  - unsigned-compare in-tile test (3 compares instead of 6).
// R10 ncu: alu=52.6% top pipe, issue=62.7% -> instruction-bound.
// |flow|>3 (~0.8%) -> exact fp32 global-path fallback.

#define Dz 160
#define Hy 192
#define Wx 160
#define Bn 2
#define HW (Hy * Wx)            // 30720
#define DHW (Dz * Hy * Wx)      // 4915200

#define RH 3                    // halo radius
#define TX 32
#define TY 16
#define TZ 8
#define EX (TX + 2 * RH + 1)    // 39
#define EY (TY + 2 * RH + 1)    // 23
#define EZ (TZ + 2 * RH + 1)    // 15
#define NROWS (EY * EZ)         // 345
#define ESZ (EX * NROWS)        // 13455
#define SMEM_BYTES (ESZ * (int)sizeof(__half2))  // 53820

#define NTHREADS 512
#define NWARPS (NTHREADS / 32)  // 16

__device__ __forceinline__ void fallback_gather(
    const float* c0, const float* c1,
    int x0, int y0, int z0,
    float fx, float fy, float fz,
    float& acc0, float& acc1)
{
    int x1 = x0 + 1, y1 = y0 + 1, z1 = z0 + 1;
    float wx0 = (x0 >= 0 && x0 < Wx) ? (1.0f - fx) : 0.0f;
    float wx1 = (x1 >= 0 && x1 < Wx) ? fx          : 0.0f;
    float wy0 = (y0 >= 0 && y0 < Hy) ? (1.0f - fy) : 0.0f;
    float wy1 = (y1 >= 0 && y1 < Hy) ? fy          : 0.0f;
    float wz0 = (z0 >= 0 && z0 < Dz) ? (1.0f - fz) : 0.0f;
    float wz1 = (z1 >= 0 && z1 < Dz) ? fz          : 0.0f;

    int x0c = min(max(x0, 0), Wx - 1);
    int x1c = min(max(x1, 0), Wx - 1);
    int y0c = min(max(y0, 0), Hy - 1);
    int y1c = min(max(y1, 0), Hy - 1);
    int z0c = min(max(z0, 0), Dz - 1);
    int z1c = min(max(z1, 0), Dz - 1);

    int zy00 = z0c * HW + y0c * Wx;
    int zy01 = z0c * HW + y1c * Wx;
    int zy10 = z1c * HW + y0c * Wx;
    int zy11 = z1c * HW + y1c * Wx;

    float w00 = wz0 * wy0, w01 = wz0 * wy1;
    float w10 = wz1 * wy0, w11 = wz1 * wy1;
    float w000 = w00 * wx0, w001 = w00 * wx1;
    float w010 = w01 * wx0, w011 = w01 * wx1;
    float w100 = w10 * wx0, w101 = w10 * wx1;
    float w110 = w11 * wx0, w111 = w11 * wx1;

    acc0  = w000 * __ldg(c0 + zy00 + x0c) + w001 * __ldg(c0 + zy00 + x1c);
    acc0 += w010 * __ldg(c0 + zy01 + x0c) + w011 * __ldg(c0 + zy01 + x1c);
    acc0 += w100 * __ldg(c0 + zy10 + x0c) + w101 * __ldg(c0 + zy10 + x1c);
    acc0 += w110 * __ldg(c0 + zy11 + x0c) + w111 * __ldg(c0 + zy11 + x1c);

    acc1  = w000 * __ldg(c1 + zy00 + x0c) + w001 * __ldg(c1 + zy00 + x1c);
    acc1 += w010 * __ldg(c1 + zy01 + x0c) + w011 * __ldg(c1 + zy01 + x1c);
    acc1 += w100 * __ldg(c1 + zy10 + x0c) + w101 * __ldg(c1 + zy10 + x1c);
    acc1 += w110 * __ldg(c1 + zy11 + x0c) + w111 * __ldg(c1 + zy11 + x1c);
}

template <bool INTERIOR>
__device__ __forceinline__ void gather_loop(
    const __half2* __restrict__ tile,
    const float* __restrict__ c0, const float* __restrict__ c1,
    const float* __restrict__ fb, float* __restrict__ ob,
    int w, int h, int bz, int x_org, int y_org, int z_org)
{
    int s_base = ((bz * TZ) * Hy + h) * Wx + w;

    #pragma unroll
    for (int kz = 0; kz < TZ; kz++) {
        int d = bz * TZ + kz;
        int s = s_base + kz * HW;

        float x = (float)w + __ldg(fb + s);
        float y = (float)h + __ldg(fb + s + DHW);
        float z = (float)d + __ldg(fb + s + 2 * DHW);

        float x0f = floorf(x), y0f = floorf(y), z0f = floorf(z);
        float fx = x - x0f, fy = y - y0f, fz = z - z0f;
        int x0 = (int)x0f, y0 = (int)y0f, z0 = (int)z0f;

        int lx = x0 - x_org;
        int ly = y0 - y_org;
        int lz = z0 - z_org;

        float acc0, acc1;
        // In-tile test via unsigned trick: lx in [0, EX-2] etc.
        if ((unsigned)lx < (unsigned)(EX - 1) &&
            (unsigned)ly < (unsigned)(EY - 1) &&
            (unsigned)lz < (unsigned)(EZ - 1)) {
            float wx0, wx1, wy0, wy1, wz0, wz1;
            if (INTERIOR) {
                // Tile strictly inside volume: in-tile implies in-volume.
                wx0 = 1.0f - fx; wx1 = fx;
                wy0 = 1.0f - fy; wy1 = fy;
                wz0 = 1.0f - fz; wz1 = fz;
            } else {
                wx0 = (x0 >= 0 && x0 < Wx)         ? (1.0f - fx) : 0.0f;
                wx1 = (x0 + 1 >= 0 && x0 + 1 < Wx) ? fx          : 0.0f;
                wy0 = (y0 >= 0 && y0 < Hy)         ? (1.0f - fy) : 0.0f;
                wy1 = (y0 + 1 >= 0 && y0 + 1 < Hy) ? fy          : 0.0f;
                wz0 = (z0 >= 0 && z0 < Dz)         ? (1.0f - fz) : 0.0f;
                wz1 = (z0 + 1 >= 0 && z0 + 1 < Dz) ? fz          : 0.0f;
            }

            float w00 = wz0 * wy0, w01 = wz0 * wy1;
            float w10 = wz1 * wy0, w11 = wz1 * wy1;

            const __half2* t00 = tile + (lz * EY + ly) * EX + lx;
            const __half2* t10 = t00 + EY * EX;
            float2 v000 = __half22float2(t00[0]);
            float2 v001 = __half22float2(t00[1]);
            float2 v010 = __half22float2(t00[EX]);
            float2 v011 = __half22float2(t00[EX + 1]);
            float2 v100 = __half22float2(t10[0]);
            float2 v101 = __half22float2(t10[1]);
            float2 v110 = __half22float2(t10[EX]);
            float2 v111 = __half22float2(t10[EX + 1]);

            float lo0 = w00 * v000.x + w01 * v010.x + w10 * v100.x + w11 * v110.x;
            float hi0 = w00 * v001.x + w01 * v011.x + w10 * v101.x + w11 * v111.x;
            float lo1 = w00 * v000.y + w01 * v010.y + w10 * v100.y + w11 * v110.y;
            float hi1 = w00 * v001.y + w01 * v011.y + w10 * v101.y + w11 * v111.y;

            acc0 = wx0 * lo0 + wx1 * hi0;
            acc1 = wx0 * lo1 + wx1 * hi1;
        } else {
            fallback_gather(c0, c1, x0, y0, z0, fx, fy, fz, acc0, acc1);
        }

        ob[s] = acc0;
        ob[DHW + s] = acc1;
    }
}

__global__ __launch_bounds__(NTHREADS, 3) void warp3d_tiled(
    const float* __restrict__ src,
    const float* __restrict__ flow,
    float* __restrict__ out)
{
    extern __shared__ __half2 tile[];

    int bx = blockIdx.x;            // 0..4
    int by = blockIdx.y;            // 0..11
    int bzb = blockIdx.z;           // 0..39
    int b  = bzb / (Dz / TZ);
    int bz = bzb % (Dz / TZ);

    int x_org = bx * TX - RH;
    int y_org = by * TY - RH;
    int z_org = bz * TZ - RH;

    const float* c0 = src + (size_t)b * 2 * DHW;
    const float* c1 = c0 + DHW;

    int lane = threadIdx.x & 31;
    int warp = threadIdx.x >> 5;    // 0..15

    // ---- Fill: each warp copies whole (ez,ey) rows, coalesced strips ----
    for (int r = warp; r < NROWS; r += NWARPS) {
        int ey = r % EY;
        int ez = r / EY;
        int gy = min(max(y_org + ey, 0), Hy - 1);
        int gz = min(max(z_org + ez, 0), Dz - 1);
        const float* r0 = c0 + (gz * Hy + gy) * Wx;
        const float* r1 = c1 + (gz * Hy + gy) * Wx;
        __half2* trow = tile + r * EX;

        int gx0 = min(max(x_org + lane, 0), Wx - 1);
        trow[lane] = __floats2half2_rn(__ldg(r0 + gx0), __ldg(r1 + gx0));
        int ex = lane + 32;
        if (ex < EX) {
            int gx1 = min(max(x_org + ex, 0), Wx - 1);
            trow[ex] = __floats2half2_rn(__ldg(r0 + gx1), __ldg(r1 + gx1));
        }
    }
    __syncthreads();

    int w = bx * TX + lane;
    int h = by * TY + warp;
    const float* fb = flow + (size_t)b * 3 * DHW;
    float* ob = out + (size_t)b * 2 * DHW;

    bool interior = (x_org >= 0) && (x_org + EX <= Wx) &&
                    (y_org >= 0) && (y_org + EY <= Hy) &&
                    (z_org >= 0) && (z_org + EZ <= Dz);

    if (interior)
        gather_loop<true>(tile, c0, c1, fb, ob, w, h, bz, x_org, y_org, z_org);
    else
        gather_loop<false>(tile, c0, c1, fb, ob, w, h, bz, x_org, y_org, z_org);
}

extern "C" void kernel_launch(void* const* d_in, const int* in_sizes, int n_in,
                              void* d_out, int out_size) {
    const float* src  = (const float*)d_in[0];
    const float* flow = (const float*)d_in[1];
    float* out = (float*)d_out;

    cudaFuncSetAttribute(warp3d_tiled,
                         cudaFuncAttributeMaxDynamicSharedMemorySize, SMEM_BYTES);

    dim3 grid(Wx / TX, Hy / TY, (Dz / TZ) * Bn);
    warp3d_tiled<<<grid, NTHREADS, SMEM_BYTES>>>(src, flow, out);
}

// round 12
// speedup vs baseline: 1.5625x; 1.0058x over previous
#include <cuda_runtime.h>
#include <cuda_fp16.h>

// SpatialTransformer: out[b,c,d,h,w] = trilinear_sample(src[b,c], (w,h,d)+flow[b,:,d,h,w])
// align_corners=True normalization cancels; padding_mode='zeros'.
//
// R12: R11 + HFMA2 zy-blend. R11 ncu: alu=54.8%/issue=67% instruction-bound;
// hot path spent 16 F2F cvts + 16 fp32 FMA on the blend. Now: pack 4 zy-weights
// to broadcast half2 (4 ops), blend both channels per corner with HMUL2/HFMA2
// (8 ops), convert only lo/hi (4 F2F), finish x-blend in fp32. ~12 fewer issue
// slots/voxel. Values were already fp16; added fp16 arithmetic error ~2e-4.
// |flow|>3 (~0.8%) -> exact fp32 global-path fallback.

#define Dz 160
#define Hy 192
#define Wx 160
#define Bn 2
#define HW (Hy * Wx)            // 30720
#define DHW (Dz * Hy * Wx)      // 4915200

#define RH 3                    // halo radius
#define TX 32
#define TY 16
#define TZ 8
#define EX (TX + 2 * RH + 1)    // 39
#define EY (TY + 2 * RH + 1)    // 23
#define EZ (TZ + 2 * RH + 1)    // 15
#define NROWS (EY * EZ)         // 345
#define ESZ (EX * NROWS)        // 13455
#define SMEM_BYTES (ESZ * (int)sizeof(__half2))  // 53820

#define NTHREADS 512
#define NWARPS (NTHREADS / 32)  // 16

__device__ __forceinline__ void fallback_gather(
    const float* c0, const float* c1,
    int x0, int y0, int z0,
    float fx, float fy, float fz,
    float& acc0, float& acc1)
{
    int x1 = x0 + 1, y1 = y0 + 1, z1 = z0 + 1;
    float wx0 = (x0 >= 0 && x0 < Wx) ? (1.0f - fx) : 0.0f;
    float wx1 = (x1 >= 0 && x1 < Wx) ? fx          : 0.0f;
    float wy0 = (y0 >= 0 && y0 < Hy) ? (1.0f - fy) : 0.0f;
    float wy1 = (y1 >= 0 && y1 < Hy) ? fy          : 0.0f;
    float wz0 = (z0 >= 0 && z0 < Dz) ? (1.0f - fz) : 0.0f;
    float wz1 = (z1 >= 0 && z1 < Dz) ? fz          : 0.0f;

    int x0c = min(max(x0, 0), Wx - 1);
    int x1c = min(max(x1, 0), Wx - 1);
    int y0c = min(max(y0, 0), Hy - 1);
    int y1c = min(max(y1, 0), Hy - 1);
    int z0c = min(max(z0, 0), Dz - 1);
    int z1c = min(max(z1, 0), Dz - 1);

    int zy00 = z0c * HW + y0c * Wx;
    int zy01 = z0c * HW + y1c * Wx;
    int zy10 = z1c * HW + y0c * Wx;
    int zy11 = z1c * HW + y1c * Wx;

    float w00 = wz0 * wy0, w01 = wz0 * wy1;
    float w10 = wz1 * wy0, w11 = wz1 * wy1;
    float w000 = w00 * wx0, w001 = w00 * wx1;
    float w010 = w01 * wx0, w011 = w01 * wx1;
    float w100 = w10 * wx0, w101 = w10 * wx1;
    float w110 = w11 * wx0, w111 = w11 * wx1;

    acc0  = w000 * __ldg(c0 + zy00 + x0c) + w001 * __ldg(c0 + zy00 + x1c);
    acc0 += w010 * __ldg(c0 + zy01 + x0c) + w011 * __ldg(c0 + zy01 + x1c);
    acc0 += w100 * __ldg(c0 + zy10 + x0c) + w101 * __ldg(c0 + zy10 + x1c);
    acc0 += w110 * __ldg(c0 + zy11 + x0c) + w111 * __ldg(c0 + zy11 + x1c);

    acc1  = w000 * __ldg(c1 + zy00 + x0c) + w001 * __ldg(c1 + zy00 + x1c);
    acc1 += w010 * __ldg(c1 + zy01 + x0c) + w011 * __ldg(c1 + zy01 + x1c);
    acc1 += w100 * __ldg(c1 + zy10 + x0c) + w101 * __ldg(c1 + zy10 + x1c);
    acc1 += w110 * __ldg(c1 + zy11 + x0c) + w111 * __ldg(c1 + zy11 + x1c);
}

template <bool INTERIOR>
__device__ __forceinline__ void gather_loop(
    const __half2* __restrict__ tile,
    const float* __restrict__ c0, const float* __restrict__ c1,
    const float* __restrict__ fb, float* __restrict__ ob,
    int w, int h, int bz, int x_org, int y_org, int z_org)
{
    int s_base = ((bz * TZ) * Hy + h) * Wx + w;

    #pragma unroll
    for (int kz = 0; kz < TZ; kz++) {
        int d = bz * TZ + kz;
        int s = s_base + kz * HW;

        float x = (float)w + __ldg(fb + s);
        float y = (float)h + __ldg(fb + s + DHW);
        float z = (float)d + __ldg(fb + s + 2 * DHW);

        float x0f = floorf(x), y0f = floorf(y), z0f = floorf(z);
        float fx = x - x0f, fy = y - y0f, fz = z - z0f;
        int x0 = (int)x0f, y0 = (int)y0f, z0 = (int)z0f;

        int lx = x0 - x_org;
        int ly = y0 - y_org;
        int lz = z0 - z_org;

        float acc0, acc1;
        if ((unsigned)lx < (unsigned)(EX - 1) &&
            (unsigned)ly < (unsigned)(EY - 1) &&
            (unsigned)lz < (unsigned)(EZ - 1)) {
            float wx0, wx1, wy0, wy1, wz0, wz1;
            if (INTERIOR) {
                wx0 = 1.0f - fx; wx1 = fx;
                wy0 = 1.0f - fy; wy1 = fy;
                wz0 = 1.0f - fz; wz1 = fz;
            } else {
                wx0 = (x0 >= 0 && x0 < Wx)         ? (1.0f - fx) : 0.0f;
                wx1 = (x0 + 1 >= 0 && x0 + 1 < Wx) ? fx          : 0.0f;
                wy0 = (y0 >= 0 && y0 < Hy)         ? (1.0f - fy) : 0.0f;
                wy1 = (y0 + 1 >= 0 && y0 + 1 < Hy) ? fy          : 0.0f;
                wz0 = (z0 >= 0 && z0 < Dz)         ? (1.0f - fz) : 0.0f;
                wz1 = (z0 + 1 >= 0 && z0 + 1 < Dz) ? fz          : 0.0f;
            }

            // zy-plane weights, broadcast to both halves (channels).
            __half2 hw00 = __float2half2_rn(wz0 * wy0);
            __half2 hw01 = __float2half2_rn(wz0 * wy1);
            __half2 hw10 = __float2half2_rn(wz1 * wy0);
            __half2 hw11 = __float2half2_rn(wz1 * wy1);

            const __half2* t00 = tile + (lz * EY + ly) * EX + lx;
            const __half2* t10 = t00 + EY * EX;

            // lo/hi = sum over 4 zy-corners, both channels per HFMA2.
            __half2 lo = __hmul2(hw00, t00[0]);
            lo = __hfma2(hw01, t00[EX],     lo);
            lo = __hfma2(hw10, t10[0],      lo);
            lo = __hfma2(hw11, t10[EX],     lo);
            __half2 hi = __hmul2(hw00, t00[1]);
            hi = __hfma2(hw01, t00[EX + 1], hi);
            hi = __hfma2(hw10, t10[1],      hi);
            hi = __hfma2(hw11, t10[EX + 1], hi);

            float2 flo = __half22float2(lo);
            float2 fhi = __half22float2(hi);

            acc0 = wx0 * flo.x + wx1 * fhi.x;
            acc1 = wx0 * flo.y + wx1 * fhi.y;
        } else {
            fallback_gather(c0, c1, x0, y0, z0, fx, fy, fz, acc0, acc1);
        }

        ob[s] = acc0;
        ob[DHW + s] = acc1;
    }
}

__global__ __launch_bounds__(NTHREADS, 3) void warp3d_tiled(
    const float* __restrict__ src,
    const float* __restrict__ flow,
    float* __restrict__ out)
{
    extern __shared__ __half2 tile[];

    int bx = blockIdx.x;            // 0..4
    int by = blockIdx.y;            // 0..11
    int bzb = blockIdx.z;           // 0..39
    int b  = bzb / (Dz / TZ);
    int bz = bzb % (Dz / TZ);

    int x_org = bx * TX - RH;
    int y_org = by * TY - RH;
    int z_org = bz * TZ - RH;

    const float* c0 = src + (size_t)b * 2 * DHW;
    const float* c1 = c0 + DHW;

    int lane = threadIdx.x & 31;
    int warp = threadIdx.x >> 5;    // 0..15

    // ---- Fill: each warp copies whole (ez,ey) rows, coalesced strips ----
    for (int r = warp; r < NROWS; r += NWARPS) {
        int ey = r % EY;
        int ez = r / EY;
        int gy = min(max(y_org + ey, 0), Hy - 1);
        int gz = min(max(z_org + ez, 0), Dz - 1);
        const float* r0 = c0 + (gz * Hy + gy) * Wx;
        const float* r1 = c1 + (gz * Hy + gy) * Wx;
        __half2* trow = tile + r * EX;

        int gx0 = min(max(x_org + lane, 0), Wx - 1);
        trow[lane] = __floats2half2_rn(__ldg(r0 + gx0), __ldg(r1 + gx0));
        int ex = lane + 32;
        if (ex < EX) {
            int gx1 = min(max(x_org + ex, 0), Wx - 1);
            trow[ex] = __floats2half2_rn(__ldg(r0 + gx1), __ldg(r1 + gx1));
        }
    }
    __syncthreads();

    int w = bx * TX + lane;
    int h = by * TY + warp;
    const float* fb = flow + (size_t)b * 3 * DHW;
    float* ob = out + (size_t)b * 2 * DHW;

    bool interior = (x_org >= 0) && (x_org + EX <= Wx) &&
                    (y_org >= 0) && (y_org + EY <= Hy) &&
                    (z_org >= 0) && (z_org + EZ <= Dz);

    if (interior)
        gather_loop<true>(tile, c0, c1, fb, ob, w, h, bz, x_org, y_org, z_org);
    else
        gather_loop<false>(tile, c0, c1, fb, ob, w, h, bz, x_org, y_org, z_org);
}

extern "C" void kernel_launch(void* const* d_in, const int* in_sizes, int n_in,
                              void* d_out, int out_size) {
    const float* src  = (const float*)d_in[0];
    const float* flow = (const float*)d_in[1];
    float* out = (float*)d_out;

    cudaFuncSetAttribute(warp3d_tiled,
                         cudaFuncAttributeMaxDynamicSharedMemorySize, SMEM_BYTES);

    dim3 grid(Wx / TX, Hy / TY, (Dz / TZ) * Bn);
    warp3d_tiled<<<grid, NTHREADS, SMEM_BYTES>>>(src, flow, out);
}